// round 1
// baseline (speedup 1.0000x reference)
#include <cuda_runtime.h>
#include <cstdint>

#define N_NODES 10000
#define NFEAT   128
#define NHID    64
#define KNN     16
#define HOPS    5

// ---------------- scratch (static device globals; no allocations) ----------
__device__ float g_P0[N_NODES * NFEAT];
__device__ float g_P1[N_NODES * NFEAT];
__device__ float g_Z [N_NODES * NFEAT];
__device__ float g_R [N_NODES * NFEAT];
__device__ float g_sq[N_NODES];
__device__ int   g_idx[N_NODES * KNN];

// ---------------- row squared norms ----------------------------------------
__global__ void __launch_bounds__(256) rownorm_kernel(const float* __restrict__ x,
                                                      float* __restrict__ sq) {
    int row  = blockIdx.x * 8 + (threadIdx.x >> 5);
    int lane = threadIdx.x & 31;
    if (row >= N_NODES) return;
    float4 v = *(const float4*)(x + (size_t)row * NFEAT + lane * 4);
    float s = v.x * v.x + v.y * v.y + v.z * v.z + v.w * v.w;
#pragma unroll
    for (int o = 16; o; o >>= 1) s += __shfl_xor_sync(0xffffffffu, s, o);
    if (lane == 0) sq[row] = s;
}

// ---------------- C = A @ B^T  (A: [M,K], B: [N,K], K multiple of 32) ------
__global__ void __launch_bounds__(256) gemm_nt_kernel(
    float* __restrict__ C, const float* __restrict__ A, const float* __restrict__ B,
    int M, int N, int K)
{
    __shared__ __align__(16) float As[32 * 132];
    __shared__ __align__(16) float Bs[32 * 132];
    const int t  = threadIdx.x;
    const int tx = t & 15, ty = t >> 4;
    const int m0 = blockIdx.y * 128, n0 = blockIdx.x * 128;

    float acc[8][8];
#pragma unroll
    for (int i = 0; i < 8; i++)
#pragma unroll
        for (int j = 0; j < 8; j++) acc[i][j] = 0.f;

    for (int k0 = 0; k0 < K; k0 += 32) {
#pragma unroll
        for (int p = 0; p < 4; p++) {
            int g = p * 256 + t;
            int row = g >> 3, kq = g & 7;
            float4 va = make_float4(0.f, 0.f, 0.f, 0.f);
            float4 vb = make_float4(0.f, 0.f, 0.f, 0.f);
            if (m0 + row < M) va = *(const float4*)(A + (size_t)(m0 + row) * K + k0 + kq * 4);
            if (n0 + row < N) vb = *(const float4*)(B + (size_t)(n0 + row) * K + k0 + kq * 4);
            As[(kq * 4 + 0) * 132 + row] = va.x;
            As[(kq * 4 + 1) * 132 + row] = va.y;
            As[(kq * 4 + 2) * 132 + row] = va.z;
            As[(kq * 4 + 3) * 132 + row] = va.w;
            Bs[(kq * 4 + 0) * 132 + row] = vb.x;
            Bs[(kq * 4 + 1) * 132 + row] = vb.y;
            Bs[(kq * 4 + 2) * 132 + row] = vb.z;
            Bs[(kq * 4 + 3) * 132 + row] = vb.w;
        }
        __syncthreads();
#pragma unroll
        for (int k = 0; k < 32; k++) {
            float a[8], b[8];
            *(float4*)(a)     = *(const float4*)(As + k * 132 + ty * 8);
            *(float4*)(a + 4) = *(const float4*)(As + k * 132 + ty * 8 + 4);
            *(float4*)(b)     = *(const float4*)(Bs + k * 132 + tx * 8);
            *(float4*)(b + 4) = *(const float4*)(Bs + k * 132 + tx * 8 + 4);
#pragma unroll
            for (int i = 0; i < 8; i++)
#pragma unroll
                for (int j = 0; j < 8; j++) acc[i][j] = fmaf(a[i], b[j], acc[i][j]);
        }
        __syncthreads();
    }
#pragma unroll
    for (int i = 0; i < 8; i++) {
        int gr = m0 + ty * 8 + i;
        if (gr < M) {
#pragma unroll
            for (int j = 0; j < 8; j++) {
                int gc = n0 + tx * 8 + j;
                if (gc < N) C[(size_t)gr * N + gc] = acc[i][j];
            }
        }
    }
}

// ------- dense propagation: C = 0.5*(adj @ B) + 0.5*x  (N fixed = 128) -----
__global__ void __launch_bounds__(256) prop_gemm_kernel(
    float* __restrict__ C, const float* __restrict__ adj,
    const float* __restrict__ B, const float* __restrict__ X,
    int M, int K)
{
    __shared__ __align__(16) float As[16 * 132];
    __shared__ __align__(16) float Bs[16 * 132];
    const int t  = threadIdx.x;
    const int tx = t & 15, ty = t >> 4;
    const int m0 = blockIdx.x * 128;

    float acc[8][8];
#pragma unroll
    for (int i = 0; i < 8; i++)
#pragma unroll
        for (int j = 0; j < 8; j++) acc[i][j] = 0.f;

    for (int k0 = 0; k0 < K; k0 += 16) {
        // A tile transposed: 128 rows x 16 k
#pragma unroll
        for (int p = 0; p < 2; p++) {
            int g = p * 256 + t;
            int row = g >> 2, kq = g & 3;
            float4 va = make_float4(0.f, 0.f, 0.f, 0.f);
            if (m0 + row < M) va = *(const float4*)(adj + (size_t)(m0 + row) * K + k0 + kq * 4);
            As[(kq * 4 + 0) * 132 + row] = va.x;
            As[(kq * 4 + 1) * 132 + row] = va.y;
            As[(kq * 4 + 2) * 132 + row] = va.z;
            As[(kq * 4 + 3) * 132 + row] = va.w;
        }
        // B tile direct: 16 rows x 128 cols
#pragma unroll
        for (int p = 0; p < 2; p++) {
            int g = p * 256 + t;
            int kr = g >> 5, cq = g & 31;
            float4 vb = *(const float4*)(B + (size_t)(k0 + kr) * 128 + cq * 4);
            *(float4*)(Bs + kr * 132 + cq * 4) = vb;
        }
        __syncthreads();
#pragma unroll
        for (int k = 0; k < 16; k++) {
            float a[8], b[8];
            *(float4*)(a)     = *(const float4*)(As + k * 132 + ty * 8);
            *(float4*)(a + 4) = *(const float4*)(As + k * 132 + ty * 8 + 4);
            *(float4*)(b)     = *(const float4*)(Bs + k * 132 + tx * 8);
            *(float4*)(b + 4) = *(const float4*)(Bs + k * 132 + tx * 8 + 4);
#pragma unroll
            for (int i = 0; i < 8; i++)
#pragma unroll
                for (int j = 0; j < 8; j++) acc[i][j] = fmaf(a[i], b[j], acc[i][j]);
        }
        __syncthreads();
    }
#pragma unroll
    for (int i = 0; i < 8; i++) {
        int gr = m0 + ty * 8 + i;
        if (gr < M) {
#pragma unroll
            for (int j = 0; j < 8; j++) {
                int gc = tx * 8 + j;   // N = 128, always in bounds
                C[(size_t)gr * 128 + gc] = 0.5f * acc[i][j] + 0.5f * X[(size_t)gr * 128 + gc];
            }
        }
    }
}

// ---------------- per-row top-16 of score = S[i][j] - 0.5*sq[j] ------------
__global__ void __launch_bounds__(256) topk_kernel(const float* __restrict__ S,
                                                   const float* __restrict__ sq,
                                                   int* __restrict__ outIdx) {
    __shared__ float sc[N_NODES];
    __shared__ float rv[256];
    __shared__ int   ri[256];
    const int i = blockIdx.x, t = threadIdx.x;

    const float4* Sr = (const float4*)(S + (size_t)i * N_NODES);
    const float4* Q  = (const float4*)sq;
    for (int q = t; q < N_NODES / 4; q += 256) {
        float4 s = Sr[q];
        float4 n = Q[q];
        float4 v = make_float4(s.x - 0.5f * n.x, s.y - 0.5f * n.y,
                               s.z - 0.5f * n.z, s.w - 0.5f * n.w);
        *(float4*)(sc + q * 4) = v;
    }
    __syncthreads();
    if (t == 0) sc[i] = -1e30f;   // exclude self
    __syncthreads();

    for (int r = 0; r < KNN; r++) {
        float bv = -3.0e38f;
        int   bi = 0x7fffffff;
        for (int j = t; j < N_NODES; j += 256) {
            float v = sc[j];
            if (v > bv) { bv = v; bi = j; }
        }
        rv[t] = bv; ri[t] = bi;
        __syncthreads();
        for (int s = 128; s; s >>= 1) {
            if (t < s) {
                float ov = rv[t + s]; int oi = ri[t + s];
                if (ov > rv[t] || (ov == rv[t] && oi < ri[t])) { rv[t] = ov; ri[t] = oi; }
            }
            __syncthreads();
        }
        if (t == 0) {
            outIdx[i * KNN + r] = ri[0];
            sc[ri[0]] = -3.0e38f;
        }
        __syncthreads();
    }
}

// -------- sparse knn propagation: out = (0.5/16)*sum_nbr h + 0.5*x ---------
__global__ void __launch_bounds__(256) knnprop_kernel(float* __restrict__ out,
                                                      const float* __restrict__ h,
                                                      const float* __restrict__ x,
                                                      const int* __restrict__ idx) {
    int gid = blockIdx.x * 256 + threadIdx.x;
    if (gid >= N_NODES * NFEAT) return;
    int i = gid >> 7, f = gid & 127;
    const int* nb = idx + i * KNN;
    float s = 0.f;
#pragma unroll
    for (int m = 0; m < KNN; m++) s += h[(size_t)nb[m] * NFEAT + f];
    out[gid] = 0.03125f * s + 0.5f * x[gid];
}

// -------- small MLP: out[:, off+cb : off+cb+64] = act(P @ W[:,cb:cb+64] + b)
// block = 128 rows x 64 cols; grid.y selects 64-col slab (cb = blockIdx.y*64)
__global__ void __launch_bounds__(256) mlp_kernel(
    float* __restrict__ out, const float* __restrict__ P,
    const float* __restrict__ W, const float* __restrict__ b,
    int M, int K, int ldP, int ldW, int ldOut, int outColOff, int doRelu)
{
    __shared__ __align__(16) float Ws[128 * 64];
    __shared__ __align__(16) float bs[64];
    const int t = threadIdx.x;
    const int cbase = blockIdx.y * 64;
    for (int q = t; q < K * 64; q += 256) {
        int k = q >> 6, c = q & 63;
        Ws[q] = W[k * ldW + cbase + c];
    }
    if (t < 64) bs[t] = b[cbase + t];
    __syncthreads();

    int r = blockIdx.x * 128 + (t >> 1);
    if (r >= M) return;
    int c0 = (t & 1) * 32;

    float4 acc[8];
#pragma unroll
    for (int u = 0; u < 8; u++) acc[u] = make_float4(0.f, 0.f, 0.f, 0.f);

    const float* p = P + (size_t)r * ldP;
    for (int k = 0; k < K; k++) {
        float pv = p[k];
        const float4* w4 = (const float4*)(Ws + (k << 6) + c0);
#pragma unroll
        for (int u = 0; u < 8; u++) {
            float4 w = w4[u];
            acc[u].x = fmaf(pv, w.x, acc[u].x);
            acc[u].y = fmaf(pv, w.y, acc[u].y);
            acc[u].z = fmaf(pv, w.z, acc[u].z);
            acc[u].w = fmaf(pv, w.w, acc[u].w);
        }
    }
    float4* o = (float4*)(out + (size_t)r * ldOut + outColOff + cbase + c0);
#pragma unroll
    for (int u = 0; u < 8; u++) {
        float4 v = acc[u];
        float4 bb = *(const float4*)(bs + c0 + u * 4);
        v.x += bb.x; v.y += bb.y; v.z += bb.z; v.w += bb.w;
        if (doRelu) {
            v.x = fmaxf(v.x, 0.f); v.y = fmaxf(v.y, 0.f);
            v.z = fmaxf(v.z, 0.f); v.w = fmaxf(v.w, 0.f);
        }
        o[u] = v;
    }
}

// ---------------------------------------------------------------------------
extern "C" void kernel_launch(void* const* d_in, const int* in_sizes, int n_in,
                              void* d_out, int out_size) {
    const float* x      = (const float*)d_in[0];
    const float* adj    = (const float*)d_in[1];
    const float* W_enc  = (const float*)d_in[2];
    const float* b_enc  = (const float*)d_in[3];
    const float* W_enc2 = (const float*)d_in[4];
    const float* b_enc2 = (const float*)d_in[5];
    const float* W_dec  = (const float*)d_in[6];
    const float* b_dec  = (const float*)d_in[7];
    (void)in_sizes; (void)n_in; (void)out_size;   // k=16, l=5 fixed by problem

    float* out = (float*)d_out;
    float* h1o = out;                                  // [10000, 64]
    float* h2o = out + (size_t)N_NODES * NHID;         // [10000, 64]
    float* G   = out + (size_t)2 * N_NODES * NHID;     // [10000, 10000]

    float *P0, *P1, *Z, *R, *SQ; int* IDX;
    cudaGetSymbolAddress((void**)&P0,  g_P0);
    cudaGetSymbolAddress((void**)&P1,  g_P1);
    cudaGetSymbolAddress((void**)&Z,   g_Z);
    cudaGetSymbolAddress((void**)&R,   g_R);
    cudaGetSymbolAddress((void**)&SQ,  g_sq);
    cudaGetSymbolAddress((void**)&IDX, g_idx);

    const int MB = (N_NODES + 127) / 128;   // 79

    // 1) row norms
    rownorm_kernel<<<(N_NODES + 7) / 8, 256>>>(x, SQ);

    // 2) S = x @ x^T  into G region (scratch; overwritten by step 10)
    gemm_nt_kernel<<<dim3(MB, MB), 256>>>(G, x, x, N_NODES, N_NODES, NFEAT);

    // 3) top-16 neighbor indices
    topk_kernel<<<N_NODES, 256>>>(G, SQ, IDX);

    // 4) dense propagation: 5 hops of 0.5*(adj@h)+0.5*x
    const float* hin = x;
    for (int it = 0; it < HOPS; it++) {
        float* ho = (it & 1) ? P1 : P0;
        prop_gemm_kernel<<<MB, 256>>>(ho, adj, hin, x, N_NODES, N_NODES);
        hin = ho;
    }
    // 5) encoder on dense-propagated features -> h1 output
    mlp_kernel<<<dim3(MB, 1), 256>>>(h1o, hin, W_enc, b_enc,
                                     N_NODES, NFEAT, NFEAT, NHID, NHID, 0, 1);

    // 6) knn propagation (sparse gather), 5 hops
    hin = x;
    for (int it = 0; it < HOPS; it++) {
        float* ho = (it & 1) ? P1 : P0;
        knnprop_kernel<<<(N_NODES * NFEAT) / 256, 256>>>(ho, hin, x, IDX);
        hin = ho;
    }
    // 7) encoder on knn-propagated features -> h2 output
    mlp_kernel<<<dim3(MB, 1), 256>>>(h2o, hin, W_enc, b_enc,
                                     N_NODES, NFEAT, NFEAT, NHID, NHID, 0, 1);

    // 8) z1 | z2 -> concat buffer Z [10000, 128]
    mlp_kernel<<<dim3(MB, 1), 256>>>(Z, h1o, W_enc2, b_enc2,
                                     N_NODES, NHID, NHID, NHID, NFEAT, 0, 1);
    mlp_kernel<<<dim3(MB, 1), 256>>>(Z, h2o, W_enc2, b_enc2,
                                     N_NODES, NHID, NHID, NHID, NFEAT, NHID, 1);

    // 9) res = Z @ W_dec + b_dec   [10000, 128]
    mlp_kernel<<<dim3(MB, 2), 256>>>(R, Z, W_dec, b_dec,
                                     N_NODES, NFEAT, NFEAT, NFEAT, NFEAT, 0, 0);

    // 10) G = res @ res^T
    gemm_nt_kernel<<<dim3(MB, MB), 256>>>(G, R, R, N_NODES, N_NODES, NFEAT);
}

// round 2
// speedup vs baseline: 1.0448x; 1.0448x over previous
#include <cuda_runtime.h>
#include <cstdint>

#define N_NODES 10000
#define NFEAT   128
#define NHID    64
#define KNN     16
#define HOPS    5

// ---------------- scratch (static device globals; no allocations) ----------
__device__ float g_P0[N_NODES * NFEAT];
__device__ float g_P1[N_NODES * NFEAT];
__device__ float g_Z [N_NODES * NFEAT];
__device__ float g_R [N_NODES * NFEAT];
__device__ float g_sq[N_NODES];
__device__ int   g_idx[N_NODES * KNN];

// ---------------- row squared norms ----------------------------------------
__global__ void __launch_bounds__(256) rownorm_kernel(const float* __restrict__ x,
                                                      float* __restrict__ sq) {
    int row  = blockIdx.x * 8 + (threadIdx.x >> 5);
    int lane = threadIdx.x & 31;
    if (row >= N_NODES) return;
    float4 v = *(const float4*)(x + (size_t)row * NFEAT + lane * 4);
    float s = v.x * v.x + v.y * v.y + v.z * v.z + v.w * v.w;
#pragma unroll
    for (int o = 16; o; o >>= 1) s += __shfl_xor_sync(0xffffffffu, s, o);
    if (lane == 0) sq[row] = s;
}

// ---------------- C = A @ B^T  (A: [M,K], B: [N,K], K multiple of 32) ------
__global__ void __launch_bounds__(256) gemm_nt_kernel(
    float* __restrict__ C, const float* __restrict__ A, const float* __restrict__ B,
    int M, int N, int K)
{
    __shared__ __align__(16) float As[32 * 132];
    __shared__ __align__(16) float Bs[32 * 132];
    const int t  = threadIdx.x;
    const int tx = t & 15, ty = t >> 4;
    const int m0 = blockIdx.y * 128, n0 = blockIdx.x * 128;

    float acc[8][8];
#pragma unroll
    for (int i = 0; i < 8; i++)
#pragma unroll
        for (int j = 0; j < 8; j++) acc[i][j] = 0.f;

    for (int k0 = 0; k0 < K; k0 += 32) {
#pragma unroll
        for (int p = 0; p < 4; p++) {
            int g = p * 256 + t;
            int row = g >> 3, kq = g & 7;
            float4 va = make_float4(0.f, 0.f, 0.f, 0.f);
            float4 vb = make_float4(0.f, 0.f, 0.f, 0.f);
            if (m0 + row < M) va = *(const float4*)(A + (size_t)(m0 + row) * K + k0 + kq * 4);
            if (n0 + row < N) vb = *(const float4*)(B + (size_t)(n0 + row) * K + k0 + kq * 4);
            As[(kq * 4 + 0) * 132 + row] = va.x;
            As[(kq * 4 + 1) * 132 + row] = va.y;
            As[(kq * 4 + 2) * 132 + row] = va.z;
            As[(kq * 4 + 3) * 132 + row] = va.w;
            Bs[(kq * 4 + 0) * 132 + row] = vb.x;
            Bs[(kq * 4 + 1) * 132 + row] = vb.y;
            Bs[(kq * 4 + 2) * 132 + row] = vb.z;
            Bs[(kq * 4 + 3) * 132 + row] = vb.w;
        }
        __syncthreads();
#pragma unroll
        for (int k = 0; k < 32; k++) {
            float a[8], b[8];
            *(float4*)(a)     = *(const float4*)(As + k * 132 + ty * 8);
            *(float4*)(a + 4) = *(const float4*)(As + k * 132 + ty * 8 + 4);
            *(float4*)(b)     = *(const float4*)(Bs + k * 132 + tx * 8);
            *(float4*)(b + 4) = *(const float4*)(Bs + k * 132 + tx * 8 + 4);
#pragma unroll
            for (int i = 0; i < 8; i++)
#pragma unroll
                for (int j = 0; j < 8; j++) acc[i][j] = fmaf(a[i], b[j], acc[i][j]);
        }
        __syncthreads();
    }
#pragma unroll
    for (int i = 0; i < 8; i++) {
        int gr = m0 + ty * 8 + i;
        if (gr < M) {
#pragma unroll
            for (int j = 0; j < 8; j++) {
                int gc = n0 + tx * 8 + j;
                if (gc < N) C[(size_t)gr * N + gc] = acc[i][j];
            }
        }
    }
}

// ------- dense propagation: C = 0.5*(adj @ B) + 0.5*x  (N fixed = 128) -----
__global__ void __launch_bounds__(256) prop_gemm_kernel(
    float* __restrict__ C, const float* __restrict__ adj,
    const float* __restrict__ B, const float* __restrict__ X,
    int M, int K)
{
    __shared__ __align__(16) float As[16 * 132];
    __shared__ __align__(16) float Bs[16 * 132];
    const int t  = threadIdx.x;
    const int tx = t & 15, ty = t >> 4;
    const int m0 = blockIdx.x * 128;

    float acc[8][8];
#pragma unroll
    for (int i = 0; i < 8; i++)
#pragma unroll
        for (int j = 0; j < 8; j++) acc[i][j] = 0.f;

    for (int k0 = 0; k0 < K; k0 += 16) {
        // A tile transposed: 128 rows x 16 k
#pragma unroll
        for (int p = 0; p < 2; p++) {
            int g = p * 256 + t;
            int row = g >> 2, kq = g & 3;
            float4 va = make_float4(0.f, 0.f, 0.f, 0.f);
            if (m0 + row < M) va = *(const float4*)(adj + (size_t)(m0 + row) * K + k0 + kq * 4);
            As[(kq * 4 + 0) * 132 + row] = va.x;
            As[(kq * 4 + 1) * 132 + row] = va.y;
            As[(kq * 4 + 2) * 132 + row] = va.z;
            As[(kq * 4 + 3) * 132 + row] = va.w;
        }
        // B tile direct: 16 rows x 128 cols
#pragma unroll
        for (int p = 0; p < 2; p++) {
            int g = p * 256 + t;
            int kr = g >> 5, cq = g & 31;
            float4 vb = *(const float4*)(B + (size_t)(k0 + kr) * 128 + cq * 4);
            *(float4*)(Bs + kr * 132 + cq * 4) = vb;
        }
        __syncthreads();
#pragma unroll
        for (int k = 0; k < 16; k++) {
            float a[8], b[8];
            *(float4*)(a)     = *(const float4*)(As + k * 132 + ty * 8);
            *(float4*)(a + 4) = *(const float4*)(As + k * 132 + ty * 8 + 4);
            *(float4*)(b)     = *(const float4*)(Bs + k * 132 + tx * 8);
            *(float4*)(b + 4) = *(const float4*)(Bs + k * 132 + tx * 8 + 4);
#pragma unroll
            for (int i = 0; i < 8; i++)
#pragma unroll
                for (int j = 0; j < 8; j++) acc[i][j] = fmaf(a[i], b[j], acc[i][j]);
        }
        __syncthreads();
    }
#pragma unroll
    for (int i = 0; i < 8; i++) {
        int gr = m0 + ty * 8 + i;
        if (gr < M) {
#pragma unroll
            for (int j = 0; j < 8; j++) {
                int gc = tx * 8 + j;   // N = 128, always in bounds
                C[(size_t)gr * 128 + gc] = 0.5f * acc[i][j] + 0.5f * X[(size_t)gr * 128 + gc];
            }
        }
    }
}

// ---------------- per-row top-16 of score = S[i][j] - 0.5*sq[j] ------------
__global__ void __launch_bounds__(256) topk_kernel(const float* __restrict__ S,
                                                   const float* __restrict__ sq,
                                                   int* __restrict__ outIdx) {
    __shared__ float sc[N_NODES];
    __shared__ float rv[256];
    __shared__ int   ri[256];
    const int i = blockIdx.x, t = threadIdx.x;

    const float4* Sr = (const float4*)(S + (size_t)i * N_NODES);
    const float4* Q  = (const float4*)sq;
    for (int q = t; q < N_NODES / 4; q += 256) {
        float4 s = Sr[q];
        float4 n = Q[q];
        float4 v = make_float4(s.x - 0.5f * n.x, s.y - 0.5f * n.y,
                               s.z - 0.5f * n.z, s.w - 0.5f * n.w);
        *(float4*)(sc + q * 4) = v;
    }
    __syncthreads();
    if (t == 0) sc[i] = -1e30f;   // exclude self
    __syncthreads();

    for (int r = 0; r < KNN; r++) {
        float bv = -3.0e38f;
        int   bi = 0x7fffffff;
        for (int j = t; j < N_NODES; j += 256) {
            float v = sc[j];
            if (v > bv) { bv = v; bi = j; }
        }
        rv[t] = bv; ri[t] = bi;
        __syncthreads();
        for (int s = 128; s; s >>= 1) {
            if (t < s) {
                float ov = rv[t + s]; int oi = ri[t + s];
                if (ov > rv[t] || (ov == rv[t] && oi < ri[t])) { rv[t] = ov; ri[t] = oi; }
            }
            __syncthreads();
        }
        if (t == 0) {
            outIdx[i * KNN + r] = ri[0];
            sc[ri[0]] = -3.0e38f;
        }
        __syncthreads();
    }
}

// -------- sparse knn propagation: out = (0.5/16)*sum_nbr h + 0.5*x ---------
__global__ void __launch_bounds__(256) knnprop_kernel(float* __restrict__ out,
                                                      const float* __restrict__ h,
                                                      const float* __restrict__ x,
                                                      const int* __restrict__ idx) {
    int gid = blockIdx.x * 256 + threadIdx.x;
    if (gid >= N_NODES * NFEAT) return;
    int i = gid >> 7, f = gid & 127;
    const int* nb = idx + i * KNN;
    float s = 0.f;
#pragma unroll
    for (int m = 0; m < KNN; m++) s += h[(size_t)nb[m] * NFEAT + f];
    out[gid] = 0.03125f * s + 0.5f * x[gid];
}

// -------- small MLP: out[:, off+cb : off+cb+64] = act(P @ W[:,cb:cb+64] + b)
// block = 128 rows x 64 cols; grid.y selects 64-col slab (cb = blockIdx.y*64)
__global__ void __launch_bounds__(256) mlp_kernel(
    float* __restrict__ out, const float* __restrict__ P,
    const float* __restrict__ W, const float* __restrict__ b,
    int M, int K, int ldP, int ldW, int ldOut, int outColOff, int doRelu)
{
    __shared__ __align__(16) float Ws[128 * 64];
    __shared__ __align__(16) float bs[64];
    const int t = threadIdx.x;
    const int cbase = blockIdx.y * 64;
    for (int q = t; q < K * 64; q += 256) {
        int k = q >> 6, c = q & 63;
        Ws[q] = W[k * ldW + cbase + c];
    }
    if (t < 64) bs[t] = b[cbase + t];
    __syncthreads();

    int r = blockIdx.x * 128 + (t >> 1);
    if (r >= M) return;
    int c0 = (t & 1) * 32;

    float4 acc[8];
#pragma unroll
    for (int u = 0; u < 8; u++) acc[u] = make_float4(0.f, 0.f, 0.f, 0.f);

    const float* p = P + (size_t)r * ldP;
    for (int k = 0; k < K; k++) {
        float pv = p[k];
        const float4* w4 = (const float4*)(Ws + (k << 6) + c0);
#pragma unroll
        for (int u = 0; u < 8; u++) {
            float4 w = w4[u];
            acc[u].x = fmaf(pv, w.x, acc[u].x);
            acc[u].y = fmaf(pv, w.y, acc[u].y);
            acc[u].z = fmaf(pv, w.z, acc[u].z);
            acc[u].w = fmaf(pv, w.w, acc[u].w);
        }
    }
    float4* o = (float4*)(out + (size_t)r * ldOut + outColOff + cbase + c0);
#pragma unroll
    for (int u = 0; u < 8; u++) {
        float4 v = acc[u];
        float4 bb = *(const float4*)(bs + c0 + u * 4);
        v.x += bb.x; v.y += bb.y; v.z += bb.z; v.w += bb.w;
        if (doRelu) {
            v.x = fmaxf(v.x, 0.f); v.y = fmaxf(v.y, 0.f);
            v.z = fmaxf(v.z, 0.f); v.w = fmaxf(v.w, 0.f);
        }
        o[u] = v;
    }
}

// ---------------------------------------------------------------------------
extern "C" void kernel_launch(void* const* d_in, const int* in_sizes, int n_in,
                              void* d_out, int out_size) {
    const float* x      = (const float*)d_in[0];
    const float* adj    = (const float*)d_in[1];
    const float* W_enc  = (const float*)d_in[2];
    const float* b_enc  = (const float*)d_in[3];
    const float* W_enc2 = (const float*)d_in[4];
    const float* b_enc2 = (const float*)d_in[5];
    const float* W_dec  = (const float*)d_in[6];
    const float* b_dec  = (const float*)d_in[7];
    (void)in_sizes; (void)n_in; (void)out_size;   // k=16, l=5 fixed by problem

    float* out = (float*)d_out;
    float* h1o = out;                                  // [10000, 64]
    float* h2o = out + (size_t)N_NODES * NHID;         // [10000, 64]
    float* G   = out + (size_t)2 * N_NODES * NHID;     // [10000, 10000]

    float *P0, *P1, *Z, *R, *SQ; int* IDX;
    cudaGetSymbolAddress((void**)&P0,  g_P0);
    cudaGetSymbolAddress((void**)&P1,  g_P1);
    cudaGetSymbolAddress((void**)&Z,   g_Z);
    cudaGetSymbolAddress((void**)&R,   g_R);
    cudaGetSymbolAddress((void**)&SQ,  g_sq);
    cudaGetSymbolAddress((void**)&IDX, g_idx);

    const int MB = (N_NODES + 127) / 128;   // 79

    // 1) row norms
    rownorm_kernel<<<(N_NODES + 7) / 8, 256>>>(x, SQ);

    // 2) S = x @ x^T  into G region (scratch; overwritten by step 10)
    gemm_nt_kernel<<<dim3(MB, MB), 256>>>(G, x, x, N_NODES, N_NODES, NFEAT);

    // 3) top-16 neighbor indices
    topk_kernel<<<N_NODES, 256>>>(G, SQ, IDX);

    // 4) dense propagation: 5 hops of 0.5*(adj@h)+0.5*x
    const float* hin = x;
    for (int it = 0; it < HOPS; it++) {
        float* ho = (it & 1) ? P1 : P0;
        prop_gemm_kernel<<<MB, 256>>>(ho, adj, hin, x, N_NODES, N_NODES);
        hin = ho;
    }
    // 5) encoder on dense-propagated features -> h1 output
    mlp_kernel<<<dim3(MB, 1), 256>>>(h1o, hin, W_enc, b_enc,
                                     N_NODES, NFEAT, NFEAT, NHID, NHID, 0, 1);

    // 6) knn propagation (sparse gather), 5 hops
    hin = x;
    for (int it = 0; it < HOPS; it++) {
        float* ho = (it & 1) ? P1 : P0;
        knnprop_kernel<<<(N_NODES * NFEAT) / 256, 256>>>(ho, hin, x, IDX);
        hin = ho;
    }
    // 7) encoder on knn-propagated features -> h2 output
    mlp_kernel<<<dim3(MB, 1), 256>>>(h2o, hin, W_enc, b_enc,
                                     N_NODES, NFEAT, NFEAT, NHID, NHID, 0, 1);

    // 8) z1 | z2 -> concat buffer Z [10000, 128]
    mlp_kernel<<<dim3(MB, 1), 256>>>(Z, h1o, W_enc2, b_enc2,
                                     N_NODES, NHID, NHID, NHID, NFEAT, 0, 1);
    mlp_kernel<<<dim3(MB, 1), 256>>>(Z, h2o, W_enc2, b_enc2,
                                     N_NODES, NHID, NHID, NHID, NFEAT, NHID, 1);

    // 9) res = Z @ W_dec + b_dec   [10000, 128]
    mlp_kernel<<<dim3(MB, 2), 256>>>(R, Z, W_dec, b_dec,
                                     N_NODES, NFEAT, NFEAT, NFEAT, NFEAT, 0, 0);

    // 10) G = res @ res^T
    gemm_nt_kernel<<<dim3(MB, MB), 256>>>(G, R, R, N_NODES, N_NODES, NFEAT);
}